// round 1
// baseline (speedup 1.0000x reference)
#include <cuda_runtime.h>

#define NPTS    4096
#define BATCH   16
#define THREADS 256
#define QT      4
#define QPB     (THREADS * QT)   // 1024 queries per block
#define QSLICES (NPTS / QPB)     // 4

// ---- packed f32x2 helpers (Blackwell; ptxas won't auto-fuse, must be PTX) ----
__device__ __forceinline__ unsigned long long pack2(float lo, float hi) {
    unsigned long long r;
    asm("mov.b64 %0, {%1, %2};" : "=l"(r) : "f"(lo), "f"(hi));
    return r;
}
__device__ __forceinline__ unsigned long long fma2(unsigned long long a,
                                                   unsigned long long b,
                                                   unsigned long long c) {
    unsigned long long d;
    asm("fma.rn.f32x2 %0, %1, %2, %3;" : "=l"(d) : "l"(a), "l"(b), "l"(c));
    return d;
}
__device__ __forceinline__ void unpack2(float& lo, float& hi, unsigned long long v) {
    asm("mov.b64 {%0, %1}, %2;" : "=f"(lo), "=f"(hi) : "l"(v));
}

__global__ void init_out_kernel(float* out) {
    if (threadIdx.x < 2) out[threadIdx.x] = 0.0f;
}

// One block: one (query-slice, batch, direction).
// dir 0: queries = pred, data = target  -> out[0]
// dir 1: queries = target, data = pred  -> out[1]
__global__ __launch_bounds__(THREADS) void chamfer_kernel(
    const float* __restrict__ pred,
    const float* __restrict__ target,
    float* __restrict__ out)
{
    __shared__ float s_x2[NPTS];   // -2 * x of data points
    __shared__ float s_y2[NPTS];   // -2 * y
    __shared__ float s_n [NPTS];   // |t|^2
    // exactly 48 KB static smem

    const int dir = blockIdx.z;
    const int b   = blockIdx.y;
    const int qs  = blockIdx.x;
    const int t   = threadIdx.x;

    const float* qbase = (dir == 0 ? pred : target) + (size_t)b * NPTS * 2;
    const float* dbase = (dir == 0 ? target : pred) + (size_t)b * NPTS * 2;

    // cooperative fill of the data cloud (coalesced float2 loads, broadcast later)
    for (int i = t; i < NPTS; i += THREADS) {
        float2 p = ((const float2*)dbase)[i];
        s_x2[i] = -2.0f * p.x;
        s_y2[i] = -2.0f * p.y;
        s_n [i] = p.x * p.x + p.y * p.y;
    }
    __syncthreads();

    // load this thread's QT query points
    unsigned long long qxx[QT], qyy[QT];
    float pn[QT], mn[QT];
#pragma unroll
    for (int q = 0; q < QT; q++) {
        int qi = qs * QPB + q * THREADS + t;
        float2 p = ((const float2*)qbase)[qi];
        qxx[q] = pack2(p.x, p.x);
        qyy[q] = pack2(p.y, p.y);
        pn[q]  = p.x * p.x + p.y * p.y;
        mn[q]  = 3.4e38f;
    }

    // reinterpret smem arrays as 64-bit pairs -> single LDS.64 broadcast per pair
    const unsigned long long* x22 = (const unsigned long long*)s_x2;
    const unsigned long long* y22 = (const unsigned long long*)s_y2;
    const unsigned long long* n22 = (const unsigned long long*)s_n;

#pragma unroll 4
    for (int jj = 0; jj < NPTS / 2; jj++) {
        unsigned long long xx = x22[jj];
        unsigned long long yy = y22[jj];
        unsigned long long nn = n22[jj];
#pragma unroll
        for (int q = 0; q < QT; q++) {
            // v = |t|^2 - 2*(qx*tx + qy*ty), two data points at once
            unsigned long long v = fma2(qxx[q], xx, nn);
            v = fma2(qyy[q], yy, v);
            float lo, hi;
            unpack2(lo, hi, v);              // register-pair alias, usually free
            mn[q] = fminf(mn[q], fminf(lo, hi));
        }
    }

    float acc = 0.0f;
#pragma unroll
    for (int q = 0; q < QT; q++) acc += mn[q] + pn[q];

    // warp reduce then one atomic per warp
#pragma unroll
    for (int off = 16; off; off >>= 1)
        acc += __shfl_xor_sync(0xffffffffu, acc, off);

    if ((t & 31) == 0)
        atomicAdd(&out[dir], acc * (1.0f / (float)(NPTS * BATCH)));
}

extern "C" void kernel_launch(void* const* d_in, const int* in_sizes, int n_in,
                              void* d_out, int out_size) {
    const float* pred   = (const float*)d_in[0];
    const float* target = (const float*)d_in[1];
    float* out = (float*)d_out;

    init_out_kernel<<<1, 32>>>(out);
    dim3 grid(QSLICES, BATCH, 2);
    chamfer_kernel<<<grid, THREADS>>>(pred, target, out);
}

// round 2
// speedup vs baseline: 1.0579x; 1.0579x over previous
#include <cuda_runtime.h>

#define NPTS    4096
#define BATCH   16
#define THREADS 256
#define QT      4
#define QPB     (THREADS * QT)   // 1024 queries per block
#define QSLICES (NPTS / QPB)     // 4
#define DS      4                // data splits per (dir,b,qslice)
#define CH      (NPTS / DS)      // 1024 data points per chunk
#define NQTOT   (2 * BATCH * NPTS)

// global scratch: per-(dir,b,query) running min of (|t|^2 - 2 q.t), encoded
// as order-preserving uint  (NO device allocation — static __device__ array)
__device__ unsigned int g_minbits[NQTOT];

// ---- packed f32x2 helpers ----
__device__ __forceinline__ unsigned long long pack2(float lo, float hi) {
    unsigned long long r;
    asm("mov.b64 %0, {%1, %2};" : "=l"(r) : "f"(lo), "f"(hi));
    return r;
}
__device__ __forceinline__ unsigned long long fma2(unsigned long long a,
                                                   unsigned long long b,
                                                   unsigned long long c) {
    unsigned long long d;
    asm("fma.rn.f32x2 %0, %1, %2, %3;" : "=l"(d) : "l"(a), "l"(b), "l"(c));
    return d;
}
__device__ __forceinline__ void unpack2(float& lo, float& hi, unsigned long long v) {
    asm("mov.b64 {%0, %1}, %2;" : "=f"(lo), "=f"(hi) : "l"(v));
}

// order-preserving float<->uint (handles negatives)
__device__ __forceinline__ unsigned int enc_f(float f) {
    unsigned int u = __float_as_uint(f);
    return u ^ ((unsigned int)((int)u >> 31) | 0x80000000u);
}
__device__ __forceinline__ float dec_f(unsigned int u) {
    unsigned int b = (u & 0x80000000u) ? (u ^ 0x80000000u) : ~u;
    return __uint_as_float(b);
}

__global__ void init_kernel(float* out) {
    int i = blockIdx.x * blockDim.x + threadIdx.x;
    if (i < NQTOT) g_minbits[i] = 0xFFFFFFFFu;
    if (i < 2) out[i] = 0.0f;
}

// One block: (query-slice, batch, dir, data-chunk). Partial min over its chunk.
__global__ __launch_bounds__(THREADS, 4) void chamfer_min_kernel(
    const float* __restrict__ pred,
    const float* __restrict__ target)
{
    __shared__ float s_x2[CH];   // -2 * x of data points
    __shared__ float s_y2[CH];   // -2 * y
    __shared__ float s_n [CH];   // |t|^2      (12 KB total)

    const int z   = blockIdx.z;
    const int dir = z & 1;
    const int ds  = z >> 1;
    const int b   = blockIdx.y;
    const int qs  = blockIdx.x;
    const int t   = threadIdx.x;

    const float* qbase = (dir == 0 ? pred : target) + (size_t)b * NPTS * 2;
    const float* dbase = (dir == 0 ? target : pred) + (size_t)b * NPTS * 2;

    // fill this chunk of the data cloud
    const float2* dchunk = (const float2*)dbase + ds * CH;
#pragma unroll
    for (int i = t; i < CH; i += THREADS) {
        float2 p = dchunk[i];
        s_x2[i] = -2.0f * p.x;
        s_y2[i] = -2.0f * p.y;
        s_n [i] = p.x * p.x + p.y * p.y;
    }
    __syncthreads();

    // load this thread's QT query points
    unsigned long long qxx[QT], qyy[QT];
    float mn[QT];
#pragma unroll
    for (int q = 0; q < QT; q++) {
        int qi = qs * QPB + q * THREADS + t;
        float2 p = ((const float2*)qbase)[qi];
        qxx[q] = pack2(p.x, p.x);
        qyy[q] = pack2(p.y, p.y);
        mn[q]  = 3.4e38f;
    }

    const unsigned long long* x22 = (const unsigned long long*)s_x2;
    const unsigned long long* y22 = (const unsigned long long*)s_y2;
    const unsigned long long* n22 = (const unsigned long long*)s_n;

#pragma unroll 4
    for (int jj = 0; jj < CH / 2; jj++) {
        unsigned long long xx = x22[jj];
        unsigned long long yy = y22[jj];
        unsigned long long nn = n22[jj];
#pragma unroll
        for (int q = 0; q < QT; q++) {
            unsigned long long v = fma2(qxx[q], xx, nn);
            v = fma2(qyy[q], yy, v);
            float lo, hi;
            unpack2(lo, hi, v);
            mn[q] = fminf(mn[q], fminf(lo, hi));   // -> FMNMX3
        }
    }

    // combine across data-chunk blocks via atomicMin on encoded bits
    const int qoff = (dir * BATCH + b) * NPTS + qs * QPB;
#pragma unroll
    for (int q = 0; q < QT; q++) {
        atomicMin(&g_minbits[qoff + q * THREADS + t], enc_f(mn[q]));
    }
}

// Final: add |q|^2 back, decode, sum-reduce per direction.
__global__ __launch_bounds__(256) void chamfer_sum_kernel(
    const float* __restrict__ pred,
    const float* __restrict__ target,
    float* __restrict__ out)
{
    const int idx = blockIdx.x * blockDim.x + threadIdx.x;   // < NQTOT
    const int dir = idx / (BATCH * NPTS);                    // uniform per block
    const int r   = idx - dir * (BATCH * NPTS);              // b*NPTS + i

    const float* qbase = (dir == 0) ? pred : target;
    float2 p = ((const float2*)qbase)[r];
    float val = dec_f(g_minbits[idx]) + p.x * p.x + p.y * p.y;

#pragma unroll
    for (int off = 16; off; off >>= 1)
        val += __shfl_xor_sync(0xffffffffu, val, off);

    __shared__ float s_part[8];
    int wid = threadIdx.x >> 5;
    if ((threadIdx.x & 31) == 0) s_part[wid] = val;
    __syncthreads();
    if (threadIdx.x == 0) {
        float acc = 0.0f;
#pragma unroll
        for (int w = 0; w < 8; w++) acc += s_part[w];
        atomicAdd(&out[dir], acc * (1.0f / (float)(NPTS * BATCH)));
    }
}

extern "C" void kernel_launch(void* const* d_in, const int* in_sizes, int n_in,
                              void* d_out, int out_size) {
    const float* pred   = (const float*)d_in[0];
    const float* target = (const float*)d_in[1];
    float* out = (float*)d_out;

    init_kernel<<<(NQTOT + 511) / 512, 512>>>(out);

    dim3 grid(QSLICES, BATCH, 2 * DS);
    chamfer_min_kernel<<<grid, THREADS>>>(pred, target);

    chamfer_sum_kernel<<<NQTOT / 256, 256>>>(pred, target, out);
}

// round 3
// speedup vs baseline: 1.2513x; 1.1828x over previous
#include <cuda_runtime.h>

#define NPTS    4096
#define BATCH   16
#define THREADS 256
#define QT      4
#define QPB     (THREADS * QT)   // 1024 queries per block
#define QSLICES (NPTS / QPB)     // 4
#define DS      8                // data splits
#define CH      (NPTS / DS)      // 512 data points per chunk
#define NQTOT   (2 * BATCH * NPTS)

// partial per-(dir,b,query) min of (|t|^2 - 2 q.t) for each data chunk.
// Plain stores -> no init pass required.  8 * 131072 * 4B = 4 MB.
__device__ float g_part[DS][NQTOT];

// ---- packed f32x2 helpers ----
__device__ __forceinline__ unsigned long long pack2(float lo, float hi) {
    unsigned long long r;
    asm("mov.b64 %0, {%1, %2};" : "=l"(r) : "f"(lo), "f"(hi));
    return r;
}
__device__ __forceinline__ unsigned long long fma2(unsigned long long a,
                                                   unsigned long long b,
                                                   unsigned long long c) {
    unsigned long long d;
    asm("fma.rn.f32x2 %0, %1, %2, %3;" : "=l"(d) : "l"(a), "l"(b), "l"(c));
    return d;
}
__device__ __forceinline__ void unpack2(float& lo, float& hi, unsigned long long v) {
    asm("mov.b64 {%0, %1}, %2;" : "=f"(lo), "=f"(hi) : "l"(v));
}

// One block: (query-slice, batch, dir, data-chunk).
__global__ __launch_bounds__(THREADS, 4) void chamfer_min_kernel(
    const float* __restrict__ pred,
    const float* __restrict__ target,
    float* __restrict__ out)
{
    // interleaved layout: group g of 4 points -> 12 floats:
    // [x2_0..x2_3][y2_0..y2_3][n_0..n_3]   (6 KB total)
    __shared__ float s_data[CH * 3];

    const int z   = blockIdx.z;
    const int dir = z & 1;
    const int ds  = z >> 1;
    const int b   = blockIdx.y;
    const int qs  = blockIdx.x;
    const int t   = threadIdx.x;

    if (z == 0 && b == 0 && qs == 0 && t < 2) out[t] = 0.0f;   // runs before sum kernel

    const float* qbase = (dir == 0 ? pred : target) + (size_t)b * NPTS * 2;
    const float* dbase = (dir == 0 ? target : pred) + (size_t)b * NPTS * 2;

    // fill this chunk (conflict-free scatter: (i/4)*12 + i%4 distinct mod 32)
    const float2* dchunk = (const float2*)dbase + ds * CH;
#pragma unroll
    for (int i = t; i < CH; i += THREADS) {
        float2 p = dchunk[i];
        int base = (i >> 2) * 12 + (i & 3);
        s_data[base]     = -2.0f * p.x;
        s_data[base + 4] = -2.0f * p.y;
        s_data[base + 8] = p.x * p.x + p.y * p.y;
    }
    __syncthreads();

    // this thread's QT query points
    unsigned long long qxx[QT], qyy[QT];
    float mn[QT];
#pragma unroll
    for (int q = 0; q < QT; q++) {
        int qi = qs * QPB + q * THREADS + t;
        float2 p = ((const float2*)qbase)[qi];
        qxx[q] = pack2(p.x, p.x);
        qyy[q] = pack2(p.y, p.y);
        mn[q]  = 3.4e38f;
    }

    const uint4* sd = (const uint4*)s_data;   // 3 x LDS.128 per 4 points

#pragma unroll 2
    for (int g = 0; g < CH / 4; g++) {
        uint4 x4 = sd[g * 3 + 0];
        uint4 y4 = sd[g * 3 + 1];
        uint4 n4 = sd[g * 3 + 2];
        unsigned long long xx01 = pack2(__uint_as_float(x4.x), __uint_as_float(x4.y));
        unsigned long long xx23 = pack2(__uint_as_float(x4.z), __uint_as_float(x4.w));
        unsigned long long yy01 = pack2(__uint_as_float(y4.x), __uint_as_float(y4.y));
        unsigned long long yy23 = pack2(__uint_as_float(y4.z), __uint_as_float(y4.w));
        unsigned long long nn01 = pack2(__uint_as_float(n4.x), __uint_as_float(n4.y));
        unsigned long long nn23 = pack2(__uint_as_float(n4.z), __uint_as_float(n4.w));
#pragma unroll
        for (int q = 0; q < QT; q++) {
            unsigned long long v0 = fma2(qxx[q], xx01, nn01);
            v0 = fma2(qyy[q], yy01, v0);
            unsigned long long v1 = fma2(qxx[q], xx23, nn23);
            v1 = fma2(qyy[q], yy23, v1);
            float a, bb, c, d;
            unpack2(a, bb, v0);
            unpack2(c, d,  v1);
            mn[q] = fminf(mn[q], fminf(a, bb));
            mn[q] = fminf(mn[q], fminf(c, d));
        }
    }

    // plain coalesced partial stores (no atomics, no init)
    const int qoff = (dir * BATCH + b) * NPTS + qs * QPB;
#pragma unroll
    for (int q = 0; q < QT; q++)
        g_part[ds][qoff + q * THREADS + t] = mn[q];
}

// Final: min over DS partials, add |q|^2, sum-reduce per direction.
__global__ __launch_bounds__(256) void chamfer_sum_kernel(
    const float* __restrict__ pred,
    const float* __restrict__ target,
    float* __restrict__ out)
{
    const int idx = blockIdx.x * blockDim.x + threadIdx.x;   // < NQTOT
    const int dir = idx / (BATCH * NPTS);                    // uniform per block
    const int r   = idx - dir * (BATCH * NPTS);

    float m = g_part[0][idx];
#pragma unroll
    for (int s = 1; s < DS; s++) m = fminf(m, g_part[s][idx]);

    const float* qbase = (dir == 0) ? pred : target;
    float2 p = ((const float2*)qbase)[r];
    float val = m + p.x * p.x + p.y * p.y;

#pragma unroll
    for (int off = 16; off; off >>= 1)
        val += __shfl_xor_sync(0xffffffffu, val, off);

    __shared__ float s_part[8];
    int wid = threadIdx.x >> 5;
    if ((threadIdx.x & 31) == 0) s_part[wid] = val;
    __syncthreads();
    if (threadIdx.x == 0) {
        float acc = 0.0f;
#pragma unroll
        for (int w = 0; w < 8; w++) acc += s_part[w];
        atomicAdd(&out[dir], acc * (1.0f / (float)(NPTS * BATCH)));
    }
}

extern "C" void kernel_launch(void* const* d_in, const int* in_sizes, int n_in,
                              void* d_out, int out_size) {
    const float* pred   = (const float*)d_in[0];
    const float* target = (const float*)d_in[1];
    float* out = (float*)d_out;

    dim3 grid(QSLICES, BATCH, 2 * DS);
    chamfer_min_kernel<<<grid, THREADS>>>(pred, target, out);

    chamfer_sum_kernel<<<NQTOT / 256, 256>>>(pred, target, out);
}

// round 4
// speedup vs baseline: 1.2570x; 1.0046x over previous
#include <cuda_runtime.h>

#define NPTS    4096
#define BATCH   16
#define THREADS 256
#define QT      8
#define QPB     (THREADS * QT)   // 2048 queries per block
#define QSLICES (NPTS / QPB)     // 2
#define DS      16               // data splits
#define CH      (NPTS / DS)      // 256 data points per chunk
#define NQTOT   (2 * BATCH * NPTS)

// Per-(dir,b,query) running min of (|t|^2 - 2 q.t), stored as ORDER-REVERSED
// uint keys combined with atomicMax. Key 0 (= BSS zero-init) loses to every
// real value, so no init kernel is needed; the sum kernel resets to 0 for the
// next graph replay.
__device__ unsigned int g_minbits[NQTOT];

// ---- packed f32x2 helpers ----
__device__ __forceinline__ unsigned long long fma2(unsigned long long a,
                                                   unsigned long long b,
                                                   unsigned long long c) {
    unsigned long long d;
    asm("fma.rn.f32x2 %0, %1, %2, %3;" : "=l"(d) : "l"(a), "l"(b), "l"(c));
    return d;
}
__device__ __forceinline__ unsigned long long pack2(float lo, float hi) {
    unsigned long long r;
    asm("mov.b64 %0, {%1, %2};" : "=l"(r) : "f"(lo), "f"(hi));
    return r;
}
__device__ __forceinline__ void unpack2(float& lo, float& hi, unsigned long long v) {
    asm("mov.b64 {%0, %1}, %2;" : "=f"(lo), "=f"(hi) : "l"(v));
}

// order-REVERSED encoding: smaller float -> larger key; key 0 = identity.
__device__ __forceinline__ unsigned int enc_min(float f) {
    unsigned int u = __float_as_uint(f);
    unsigned int e = u ^ ((unsigned int)((int)u >> 31) | 0x80000000u);  // order-preserving
    return ~e;                                                          // reversed
}
__device__ __forceinline__ float dec_min(unsigned int key) {
    unsigned int e = ~key;
    return (e & 0x80000000u) ? __uint_as_float(e ^ 0x80000000u)
                             : __uint_as_float(~e);
}

// One block: (query-slice, batch, dir, data-chunk).
__global__ __launch_bounds__(THREADS, 3) void chamfer_min_kernel(
    const float* __restrict__ pred,
    const float* __restrict__ target,
    float* __restrict__ out)
{
    // pre-packed layout, per group of 4 data points (3 x ulonglong2 = 48 B):
    //   [x2_01, x2_23][y2_01, y2_23][n_01, n_23]
    __shared__ ulonglong2 s_data[(CH / 4) * 3];   // 3 KB

    const int z   = blockIdx.z;
    const int dir = z & 1;
    const int ds  = z >> 1;
    const int b   = blockIdx.y;
    const int qs  = blockIdx.x;
    const int t   = threadIdx.x;

    if (z == 0 && b == 0 && qs == 0 && t < 2) out[t] = 0.0f;  // before sum kernel

    const float* qbase = (dir == 0 ? pred : target) + (size_t)b * NPTS * 2;
    const float* dbase = (dir == 0 ? target : pred) + (size_t)b * NPTS * 2;

    // fill this chunk: point i -> group i/4, slot i%4 (scalar float view)
    {
        float* sf = (float*)s_data;
        const float2* dchunk = (const float2*)dbase + ds * CH;
        int i = t;            // THREADS == CH: exactly one point per thread
        float2 p = dchunk[i];
        int base = (i >> 2) * 12 + (i & 3);
        sf[base]     = -2.0f * p.x;
        sf[base + 4] = -2.0f * p.y;
        sf[base + 8] = p.x * p.x + p.y * p.y;
    }
    __syncthreads();

    // this thread's QT query points
    unsigned long long qxx[QT], qyy[QT];
    float mn[QT];
#pragma unroll
    for (int q = 0; q < QT; q++) {
        int qi = qs * QPB + q * THREADS + t;
        float2 p = ((const float2*)qbase)[qi];
        qxx[q] = pack2(p.x, p.x);
        qyy[q] = pack2(p.y, p.y);
        mn[q]  = 3.4e38f;
    }

#pragma unroll 2
    for (int g = 0; g < CH / 4; g++) {
        ulonglong2 xx = s_data[g * 3 + 0];   // LDS.128 -> two ULLs, no movs
        ulonglong2 yy = s_data[g * 3 + 1];
        ulonglong2 nn = s_data[g * 3 + 2];
#pragma unroll
        for (int q = 0; q < QT; q++) {
            unsigned long long v0 = fma2(qxx[q], xx.x, nn.x);
            v0 = fma2(qyy[q], yy.x, v0);
            unsigned long long v1 = fma2(qxx[q], xx.y, nn.y);
            v1 = fma2(qyy[q], yy.y, v1);
            float a, bb, c, d;
            unpack2(a, bb, v0);
            unpack2(c, d,  v1);
            // two FMNMX3-shaped folds
            mn[q] = fminf(fminf(a, bb), mn[q]);
            mn[q] = fminf(fminf(c, d),  mn[q]);
        }
    }

    // cross-chunk combine: coalesced no-return atomics, identity-0 encoding
    const int qoff = (dir * BATCH + b) * NPTS + qs * QPB;
#pragma unroll
    for (int q = 0; q < QT; q++)
        atomicMax(&g_minbits[qoff + q * THREADS + t], enc_min(mn[q]));
}

// Final: decode min, add |q|^2, sum-reduce per direction, reset scratch.
__global__ __launch_bounds__(256) void chamfer_sum_kernel(
    const float* __restrict__ pred,
    const float* __restrict__ target,
    float* __restrict__ out)
{
    const int idx = blockIdx.x * blockDim.x + threadIdx.x;   // < NQTOT
    const int dir = idx / (BATCH * NPTS);                    // uniform per block
    const int r   = idx - dir * (BATCH * NPTS);

    float m = dec_min(g_minbits[idx]);
    g_minbits[idx] = 0u;                    // reset for next graph replay

    const float* qbase = (dir == 0) ? pred : target;
    float2 p = ((const float2*)qbase)[r];
    float val = m + p.x * p.x + p.y * p.y;

#pragma unroll
    for (int off = 16; off; off >>= 1)
        val += __shfl_xor_sync(0xffffffffu, val, off);

    __shared__ float s_part[8];
    int wid = threadIdx.x >> 5;
    if ((threadIdx.x & 31) == 0) s_part[wid] = val;
    __syncthreads();
    if (threadIdx.x == 0) {
        float acc = 0.0f;
#pragma unroll
        for (int w = 0; w < 8; w++) acc += s_part[w];
        atomicAdd(&out[dir], acc * (1.0f / (float)(NPTS * BATCH)));
    }
}

extern "C" void kernel_launch(void* const* d_in, const int* in_sizes, int n_in,
                              void* d_out, int out_size) {
    const float* pred   = (const float*)d_in[0];
    const float* target = (const float*)d_in[1];
    float* out = (float*)d_out;

    dim3 grid(QSLICES, BATCH, 2 * DS);
    chamfer_min_kernel<<<grid, THREADS>>>(pred, target, out);

    chamfer_sum_kernel<<<NQTOT / 256, 256>>>(pred, target, out);
}